// round 2
// baseline (speedup 1.0000x reference)
#include <cuda_runtime.h>
#include <math.h>

// ---------------------------------------------------------------------------
// SwinTransformerBlock — fp32 baseline for sm_100a
// B=32, H=W=56, C=384, heads=12, hd=32, window=7 (N=49), shift=3
// ---------------------------------------------------------------------------

#define BATCH   32
#define HH      56
#define CDIM    384
#define LTOK    3136        // 56*56
#define MTOK    100352      // 32*3136
#define NHEAD   12
#define HDIM    32
#define NWTOK   49
#define QKVDIM  1152
#define HIDDEN  1536
#define NWIN_B  64          // windows per batch (8x8)
#define BW      2048        // total windows

// ---- scratch (static device globals; no runtime allocation) ----
__device__ float g_xw [(size_t)MTOK * CDIM];    // LN1 + shifted window partition
__device__ float g_qkv[(size_t)MTOK * QKVDIM];  // qkv projection
__device__ float g_att[(size_t)MTOK * CDIM];    // attention output (head-merged)
__device__ float g_x1 [(size_t)MTOK * CDIM];    // shortcut + attn branch
__device__ float g_y  [(size_t)MTOK * CDIM];    // LN2 output
__device__ float g_h  [(size_t)MTOK * HIDDEN];  // fc1+gelu output

// Bijection: window-token row r -> (batch, token index in [0,3136))
// Encodes: cyclic shift by -3, 7x7 window partition (and its inverse).
__device__ __forceinline__ int win_to_tok(int r, int* bat) {
    int w = r / NWTOK, n = r % NWTOK;
    *bat = w / NWIN_B;
    int widx = w % NWIN_B;
    int wh = widx >> 3, ww = widx & 7;
    int hs = wh * 7 + n / 7;
    int ws = ww * 7 + n % 7;
    int h = hs + 3; if (h >= HH) h -= HH;
    int wc = ws + 3; if (wc >= HH) wc -= HH;
    return h * HH + wc;
}

// ---------------------------------------------------------------------------
// LayerNorm (+ optional shifted-window gather). 1 block per row, 128 threads.
// gather=1: row r is a window-token; source is x[b, tok(r), :]  (LN1 path)
// gather=0: source is src[r, :] directly                        (LN2 path)
// ---------------------------------------------------------------------------
__device__ __forceinline__ float block_sum128(float v, float* red) {
#pragma unroll
    for (int o = 16; o > 0; o >>= 1) v += __shfl_xor_sync(0xffffffffu, v, o);
    int w = threadIdx.x >> 5;
    if ((threadIdx.x & 31) == 0) red[w] = v;
    __syncthreads();
    v = red[0] + red[1] + red[2] + red[3];
    __syncthreads();
    return v;
}

__global__ void ln_kernel(const float* __restrict__ src,
                          const float* __restrict__ wgt,
                          const float* __restrict__ bias,
                          float* __restrict__ dst, int gather) {
    __shared__ float red[4];
    int r = blockIdx.x, t = threadIdx.x;
    size_t drow = (size_t)r * CDIM;
    size_t srow;
    if (gather) {
        int bat; int tok = win_to_tok(r, &bat);
        srow = ((size_t)bat * LTOK + tok) * CDIM;
    } else {
        srow = drow;
    }
    float v0 = src[srow + t];
    float v1 = src[srow + t + 128];
    float v2 = src[srow + t + 256];
    float mean = block_sum128(v0 + v1 + v2, red) * (1.0f / CDIM);
    float d0 = v0 - mean, d1 = v1 - mean, d2 = v2 - mean;
    float var = block_sum128(d0 * d0 + d1 * d1 + d2 * d2, red) * (1.0f / CDIM);
    float rstd = rsqrtf(var + 1e-5f);
    dst[drow + t]       = d0 * rstd * wgt[t]       + bias[t];
    dst[drow + t + 128] = d1 * rstd * wgt[t + 128] + bias[t + 128];
    dst[drow + t + 256] = d2 * rstd * wgt[t + 256] + bias[t + 256];
}

// ---------------------------------------------------------------------------
// SGEMM: C[M,N] = A[M,K] @ B[K,N] (+ bias, + epilogue)
// 128x128 tile, BK=8, 256 threads, 8x8 per-thread microtile.
// All shapes here are exact multiples (M%128==0, N%128==0, K%8==0): no guards.
// EPI 0: C = acc + bias                       (qkv)
// EPI 1: C = gelu(acc + bias)                 (fc1, exact erf-based gelu)
// EPI 2: C = acc + bias + res[r*N+c]          (fc2 + residual -> d_out)
// EPI 3: scatter (window reverse + unshift): C[b,tok,c] = acc+bias+res[b,tok,c]
// ---------------------------------------------------------------------------
template <int EPI>
__global__ void __launch_bounds__(256)
sgemm_kernel(const float* __restrict__ A, const float* __restrict__ Bm,
             const float* __restrict__ bias, float* __restrict__ Cout,
             const float* __restrict__ res, int Kdim, int Ndim) {
    __shared__ float As[8][128];
    __shared__ float Bs[8][128];

    const int t    = threadIdx.x;
    const int row0 = blockIdx.y * 128;
    const int col0 = blockIdx.x * 128;
    const int tx   = t & 15, ty = t >> 4;
    const int arow = t >> 1, acol = (t & 1) << 2;
    const int brow = t >> 5, bcol = (t & 31) << 2;

    const float* Ap = A  + (size_t)(row0 + arow) * Kdim + acol;
    const float* Bp = Bm + (size_t)brow * Ndim + col0 + bcol;

    float acc[8][8];
#pragma unroll
    for (int i = 0; i < 8; i++)
#pragma unroll
        for (int j = 0; j < 8; j++) acc[i][j] = 0.0f;

    for (int k0 = 0; k0 < Kdim; k0 += 8) {
        float4 av = *reinterpret_cast<const float4*>(Ap + k0);
        float4 bv = *reinterpret_cast<const float4*>(Bp + (size_t)k0 * Ndim);
        As[acol + 0][arow] = av.x;
        As[acol + 1][arow] = av.y;
        As[acol + 2][arow] = av.z;
        As[acol + 3][arow] = av.w;
        *reinterpret_cast<float4*>(&Bs[brow][bcol]) = bv;
        __syncthreads();
#pragma unroll
        for (int kk = 0; kk < 8; kk++) {
            float a[8], b[8];
            *reinterpret_cast<float4*>(&a[0]) = *reinterpret_cast<const float4*>(&As[kk][ty * 8]);
            *reinterpret_cast<float4*>(&a[4]) = *reinterpret_cast<const float4*>(&As[kk][ty * 8 + 4]);
            *reinterpret_cast<float4*>(&b[0]) = *reinterpret_cast<const float4*>(&Bs[kk][tx * 8]);
            *reinterpret_cast<float4*>(&b[4]) = *reinterpret_cast<const float4*>(&Bs[kk][tx * 8 + 4]);
#pragma unroll
            for (int i = 0; i < 8; i++)
#pragma unroll
                for (int j = 0; j < 8; j++) acc[i][j] += a[i] * b[j];
        }
        __syncthreads();
    }

#pragma unroll
    for (int i = 0; i < 8; i++) {
        int r = row0 + ty * 8 + i;
        size_t obase;
        if (EPI == 3) {
            int bat; int tok = win_to_tok(r, &bat);
            obase = ((size_t)bat * LTOK + tok) * CDIM;
        } else {
            obase = (size_t)r * Ndim;
        }
#pragma unroll
        for (int j = 0; j < 8; j++) {
            int c = col0 + tx * 8 + j;
            float v = acc[i][j] + bias[c];
            if (EPI == 1) v = v * normcdff(v);           // exact GELU
            if (EPI == 2) v += res[(size_t)r * Ndim + c];
            if (EPI == 3) v += res[obase + c];
            Cout[obase + c] = v;
        }
    }
}

// ---------------------------------------------------------------------------
// Windowed attention. One block per (window, head). 64 threads.
// q/k/v tiles in smem; rel-pos-bias index and shift mask computed inline.
// Scores kept in smem (s[t][m], stride 49 -> conflict-free) so loops can
// stay rolled without local-memory spills.
// ---------------------------------------------------------------------------
__global__ void __launch_bounds__(64)
attn_kernel(const float* __restrict__ qkv, const float* __restrict__ rpb,
            float* __restrict__ out) {
    __shared__ float qs[NWTOK][HDIM + 1];
    __shared__ float ks[NWTOK][HDIM + 1];
    __shared__ float vs[NWTOK][HDIM + 1];
    __shared__ float sbuf[64][NWTOK];
    __shared__ int   lab[NWTOK];

    int blk  = blockIdx.x;
    int w    = blk / NHEAD;
    int head = blk % NHEAD;
    int t    = threadIdx.x;

    const float scale = 0.17677669529663687f;  // 32^-0.5
    size_t base = (size_t)w * NWTOK * QKVDIM + head * HDIM;

    for (int idx = t; idx < NWTOK * HDIM; idx += 64) {
        int n = idx >> 5, d = idx & 31;
        size_t o = base + (size_t)n * QKVDIM + d;
        qs[n][d] = qkv[o] * scale;
        ks[n][d] = qkv[o + CDIM];
        vs[n][d] = qkv[o + 2 * CDIM];
    }
    if (t < NWTOK) {
        int widx = w % NWIN_B;
        int wh = widx >> 3, ww = widx & 7;
        int hg = wh * 7 + t / 7;
        int wg = ww * 7 + t % 7;
        int lh = (hg >= 53) ? 2 : (hg >= 49 ? 1 : 0);
        int lw = (wg >= 53) ? 2 : (wg >= 49 ? 1 : 0);
        lab[t] = lh * 3 + lw;
    }
    __syncthreads();

    if (t < NWTOK) {
        int n = t, i0 = n / 7, j0 = n % 7;
        float qn[HDIM];
#pragma unroll
        for (int d = 0; d < HDIM; d++) qn[d] = qs[n][d];

        int ln = lab[n];
        float mx = -1e30f;
        for (int m = 0; m < NWTOK; m++) {
            float acc = 0.0f;
#pragma unroll
            for (int d = 0; d < HDIM; d++) acc += qn[d] * ks[m][d];
            int i1 = m / 7, j1 = m % 7;
            acc += rpb[((i0 - i1 + 6) * 13 + (j0 - j1 + 6)) * NHEAD + head];
            if (lab[m] != ln) acc -= 100.0f;
            sbuf[t][m] = acc;
            mx = fmaxf(mx, acc);
        }
        float sum = 0.0f;
        for (int m = 0; m < NWTOK; m++) {
            float e = expf(sbuf[t][m] - mx);
            sbuf[t][m] = e;
            sum += e;
        }
        float inv = 1.0f / sum;

        float o[HDIM];
#pragma unroll
        for (int d = 0; d < HDIM; d++) o[d] = 0.0f;
        for (int m = 0; m < NWTOK; m++) {
            float p = sbuf[t][m] * inv;
#pragma unroll
            for (int d = 0; d < HDIM; d++) o[d] += p * vs[m][d];
        }
        size_t orow = ((size_t)w * NWTOK + n) * CDIM + head * HDIM;
#pragma unroll
        for (int d = 0; d < HDIM; d++) out[orow + d] = o[d];
    }
}

// ---------------------------------------------------------------------------
// launch
// ---------------------------------------------------------------------------
extern "C" void kernel_launch(void* const* d_in, const int* in_sizes, int n_in,
                              void* d_out, int out_size) {
    const float* x     = (const float*)d_in[0];
    const float* n1w   = (const float*)d_in[1];
    const float* n1b   = (const float*)d_in[2];
    const float* qkvw  = (const float*)d_in[3];
    const float* qkvb  = (const float*)d_in[4];
    const float* rpb   = (const float*)d_in[5];
    const float* projw = (const float*)d_in[6];
    const float* projb = (const float*)d_in[7];
    const float* n2w   = (const float*)d_in[8];
    const float* n2b   = (const float*)d_in[9];
    const float* fc1w  = (const float*)d_in[10];
    const float* fc1b  = (const float*)d_in[11];
    const float* fc2w  = (const float*)d_in[12];
    const float* fc2b  = (const float*)d_in[13];
    float* out = (float*)d_out;

    float *p_xw, *p_qkv, *p_att, *p_x1, *p_y, *p_h;
    cudaGetSymbolAddress((void**)&p_xw,  g_xw);
    cudaGetSymbolAddress((void**)&p_qkv, g_qkv);
    cudaGetSymbolAddress((void**)&p_att, g_att);
    cudaGetSymbolAddress((void**)&p_x1,  g_x1);
    cudaGetSymbolAddress((void**)&p_y,   g_y);
    cudaGetSymbolAddress((void**)&p_h,   g_h);

    // 1) LN1 + cyclic shift + window partition
    ln_kernel<<<MTOK, 128>>>(x, n1w, n1b, p_xw, 1);

    // 2) QKV: [100352,384] @ [384,1152]
    sgemm_kernel<0><<<dim3(QKVDIM / 128, MTOK / 128), 256>>>(
        p_xw, qkvw, qkvb, p_qkv, nullptr, CDIM, QKVDIM);

    // 3) Windowed attention (2048 windows x 12 heads)
    attn_kernel<<<BW * NHEAD, 64>>>(p_qkv, rpb, p_att);

    // 4) Proj + window reverse + unshift + residual
    sgemm_kernel<3><<<dim3(CDIM / 128, MTOK / 128), 256>>>(
        p_att, projw, projb, p_x1, x, CDIM, CDIM);

    // 5) LN2
    ln_kernel<<<MTOK, 128>>>(p_x1, n2w, n2b, p_y, 0);

    // 6) fc1 + exact GELU: [100352,384] @ [384,1536]
    sgemm_kernel<1><<<dim3(HIDDEN / 128, MTOK / 128), 256>>>(
        p_y, fc1w, fc1b, p_h, nullptr, CDIM, HIDDEN);

    // 7) fc2 + residual -> output: [100352,1536] @ [1536,384]
    sgemm_kernel<2><<<dim3(CDIM / 128, MTOK / 128), 256>>>(
        p_h, fc2w, fc2b, out, p_x1, HIDDEN, CDIM);
}

// round 3
// speedup vs baseline: 1.1854x; 1.1854x over previous
#include <cuda_runtime.h>
#include <mma.h>
#include <math.h>

using namespace nvcuda;

// ---------------------------------------------------------------------------
// SwinTransformerBlock — tf32 tensor-core GEMMs (wmma) for sm_100a
// B=32, H=W=56, C=384, heads=12, hd=32, window=7 (N=49), shift=3
// ---------------------------------------------------------------------------

#define BATCH   32
#define HH      56
#define CDIM    384
#define LTOK    3136
#define MTOK    100352
#define NHEAD   12
#define HDIM    32
#define NWTOK   49
#define QKVDIM  1152
#define HIDDEN  1536
#define NWIN_B  64
#define BW      2048

// ---- scratch ----
__device__ float g_xw [(size_t)MTOK * CDIM];
__device__ float g_qkv[(size_t)MTOK * QKVDIM];
__device__ float g_att[(size_t)MTOK * CDIM];
__device__ float g_x1 [(size_t)MTOK * CDIM];
__device__ float g_y  [(size_t)MTOK * CDIM];
__device__ float g_h  [(size_t)MTOK * HIDDEN];

__device__ __forceinline__ int win_to_tok(int r, int* bat) {
    int w = r / NWTOK, n = r % NWTOK;
    *bat = w / NWIN_B;
    int widx = w % NWIN_B;
    int wh = widx >> 3, ww = widx & 7;
    int hs = wh * 7 + n / 7;
    int ws = ww * 7 + n % 7;
    int h = hs + 3; if (h >= HH) h -= HH;
    int wc = ws + 3; if (wc >= HH) wc -= HH;
    return h * HH + wc;
}

// ---------------------------------------------------------------------------
// LayerNorm (+ optional shifted-window gather)
// ---------------------------------------------------------------------------
__device__ __forceinline__ float block_sum128(float v, float* red) {
#pragma unroll
    for (int o = 16; o > 0; o >>= 1) v += __shfl_xor_sync(0xffffffffu, v, o);
    int w = threadIdx.x >> 5;
    if ((threadIdx.x & 31) == 0) red[w] = v;
    __syncthreads();
    v = red[0] + red[1] + red[2] + red[3];
    __syncthreads();
    return v;
}

__global__ void ln_kernel(const float* __restrict__ src,
                          const float* __restrict__ wgt,
                          const float* __restrict__ bias,
                          float* __restrict__ dst, int gather) {
    __shared__ float red[4];
    int r = blockIdx.x, t = threadIdx.x;
    size_t drow = (size_t)r * CDIM;
    size_t srow;
    if (gather) {
        int bat; int tok = win_to_tok(r, &bat);
        srow = ((size_t)bat * LTOK + tok) * CDIM;
    } else {
        srow = drow;
    }
    float v0 = src[srow + t];
    float v1 = src[srow + t + 128];
    float v2 = src[srow + t + 256];
    float mean = block_sum128(v0 + v1 + v2, red) * (1.0f / CDIM);
    float d0 = v0 - mean, d1 = v1 - mean, d2 = v2 - mean;
    float var = block_sum128(d0 * d0 + d1 * d1 + d2 * d2, red) * (1.0f / CDIM);
    float rstd = rsqrtf(var + 1e-5f);
    dst[drow + t]       = d0 * rstd * wgt[t]       + bias[t];
    dst[drow + t + 128] = d1 * rstd * wgt[t + 128] + bias[t + 128];
    dst[drow + t + 256] = d2 * rstd * wgt[t + 256] + bias[t + 256];
}

// ---------------------------------------------------------------------------
// TF32 tensor-core GEMM: C[M,N] = A[M,K] @ B[K,N] (+bias +epilogue)
// 128x128 tile, BK=32, 256 threads = 8 warps, warp tile 64x32 (4x2 wmma frags
// of m16n16k8). A/B converted to tf32 on smem store. Per-warp 16x16 staging
// for fused epilogues.
// EPI 0: +bias | 1: gelu(+bias) | 2: +bias+res | 3: +bias+res, scatter rows
// ---------------------------------------------------------------------------
#define LDA 40
#define LDB 136

template <int EPI>
__global__ void __launch_bounds__(256)
tgemm_kernel(const float* __restrict__ A, const float* __restrict__ Bm,
             const float* __restrict__ bias, float* __restrict__ Cout,
             const float* __restrict__ res, int Kdim, int Ndim) {
    __shared__ float As[128 * LDA];
    __shared__ float Bs[32 * LDB];
    __shared__ float stage[8 * 256];

    const int t    = threadIdx.x;
    const int lane = t & 31;
    const int warp = t >> 5;
    const int wm   = warp >> 2;       // 0..1 (row block of 64)
    const int wn   = warp & 3;        // 0..3 (col block of 32)
    const int row0 = blockIdx.y * 128;
    const int col0 = blockIdx.x * 128;

    wmma::fragment<wmma::accumulator, 16, 16, 8, float> acc[4][2];
#pragma unroll
    for (int i = 0; i < 4; i++)
#pragma unroll
        for (int j = 0; j < 2; j++) wmma::fill_fragment(acc[i][j], 0.0f);

    for (int k0 = 0; k0 < Kdim; k0 += 32) {
        // load A tile 128x32 (1024 float4, 4 per thread), convert to tf32
#pragma unroll
        for (int i = 0; i < 4; i++) {
            int idx = t + 256 * i;
            int r = idx >> 3, c4 = (idx & 7) << 2;
            float4 v = *reinterpret_cast<const float4*>(
                A + (size_t)(row0 + r) * Kdim + k0 + c4);
            float* s = As + r * LDA + c4;
            s[0] = wmma::__float_to_tf32(v.x);
            s[1] = wmma::__float_to_tf32(v.y);
            s[2] = wmma::__float_to_tf32(v.z);
            s[3] = wmma::__float_to_tf32(v.w);
        }
        // load B tile 32x128
#pragma unroll
        for (int i = 0; i < 4; i++) {
            int idx = t + 256 * i;
            int r = idx >> 5, c4 = (idx & 31) << 2;
            float4 v = *reinterpret_cast<const float4*>(
                Bm + (size_t)(k0 + r) * Ndim + col0 + c4);
            float* s = Bs + r * LDB + c4;
            s[0] = wmma::__float_to_tf32(v.x);
            s[1] = wmma::__float_to_tf32(v.y);
            s[2] = wmma::__float_to_tf32(v.z);
            s[3] = wmma::__float_to_tf32(v.w);
        }
        __syncthreads();

#pragma unroll
        for (int kk = 0; kk < 4; kk++) {
            wmma::fragment<wmma::matrix_a, 16, 16, 8, wmma::precision::tf32,
                           wmma::row_major> af[4];
            wmma::fragment<wmma::matrix_b, 16, 16, 8, wmma::precision::tf32,
                           wmma::row_major> bf[2];
#pragma unroll
            for (int i = 0; i < 4; i++)
                wmma::load_matrix_sync(af[i],
                    As + (wm * 64 + i * 16) * LDA + kk * 8, LDA);
#pragma unroll
            for (int j = 0; j < 2; j++)
                wmma::load_matrix_sync(bf[j],
                    Bs + (kk * 8) * LDB + wn * 32 + j * 16, LDB);
#pragma unroll
            for (int i = 0; i < 4; i++)
#pragma unroll
                for (int j = 0; j < 2; j++)
                    wmma::mma_sync(acc[i][j], af[i], bf[j], acc[i][j]);
        }
        __syncthreads();
    }

    // epilogue: stage each 16x16 fragment, apply fused ops, write out
    float* stg = stage + warp * 256;
    const int lrow = lane >> 1;
    const int lcol = (lane & 1) << 3;
#pragma unroll
    for (int i = 0; i < 4; i++) {
        int r = row0 + wm * 64 + i * 16 + lrow;
        size_t obase;
        int bat, tok;
        if (EPI == 3) {
            tok = win_to_tok(r, &bat);
            obase = ((size_t)bat * LTOK + tok) * CDIM;
        } else {
            obase = (size_t)r * Ndim;
        }
#pragma unroll
        for (int j = 0; j < 2; j++) {
            wmma::store_matrix_sync(stg, acc[i][j], 16, wmma::mem_row_major);
            __syncwarp();
            int c = col0 + wn * 32 + j * 16 + lcol;
            const float* sp = stg + lrow * 16 + lcol;
            float v[8];
#pragma unroll
            for (int e = 0; e < 8; e++) {
                float x = sp[e] + bias[c + e];
                if (EPI == 1) x = x * normcdff(x);
                if (EPI == 2) x += res[(size_t)r * Ndim + c + e];
                if (EPI == 3) x += res[obase + c + e];
                v[e] = x;
            }
            float4* op = reinterpret_cast<float4*>(Cout + obase + c);
            op[0] = make_float4(v[0], v[1], v[2], v[3]);
            op[1] = make_float4(v[4], v[5], v[6], v[7]);
            __syncwarp();
        }
    }
}

// ---------------------------------------------------------------------------
// Windowed attention (fp32, unchanged from R2 — ~small fraction of runtime)
// ---------------------------------------------------------------------------
__global__ void __launch_bounds__(64)
attn_kernel(const float* __restrict__ qkv, const float* __restrict__ rpb,
            float* __restrict__ out) {
    __shared__ float qs[NWTOK][HDIM + 1];
    __shared__ float ks[NWTOK][HDIM + 1];
    __shared__ float vs[NWTOK][HDIM + 1];
    __shared__ float sbuf[64][NWTOK];
    __shared__ int   lab[NWTOK];

    int blk  = blockIdx.x;
    int w    = blk / NHEAD;
    int head = blk % NHEAD;
    int t    = threadIdx.x;

    const float scale = 0.17677669529663687f;
    size_t base = (size_t)w * NWTOK * QKVDIM + head * HDIM;

    for (int idx = t; idx < NWTOK * HDIM; idx += 64) {
        int n = idx >> 5, d = idx & 31;
        size_t o = base + (size_t)n * QKVDIM + d;
        qs[n][d] = qkv[o] * scale;
        ks[n][d] = qkv[o + CDIM];
        vs[n][d] = qkv[o + 2 * CDIM];
    }
    if (t < NWTOK) {
        int widx = w % NWIN_B;
        int wh = widx >> 3, ww = widx & 7;
        int hg = wh * 7 + t / 7;
        int wg = ww * 7 + t % 7;
        int lh = (hg >= 53) ? 2 : (hg >= 49 ? 1 : 0);
        int lw = (wg >= 53) ? 2 : (wg >= 49 ? 1 : 0);
        lab[t] = lh * 3 + lw;
    }
    __syncthreads();

    if (t < NWTOK) {
        int n = t, i0 = n / 7, j0 = n % 7;
        float qn[HDIM];
#pragma unroll
        for (int d = 0; d < HDIM; d++) qn[d] = qs[n][d];

        int ln = lab[n];
        float mx = -1e30f;
        for (int m = 0; m < NWTOK; m++) {
            float acc = 0.0f;
#pragma unroll
            for (int d = 0; d < HDIM; d++) acc += qn[d] * ks[m][d];
            int i1 = m / 7, j1 = m % 7;
            acc += rpb[((i0 - i1 + 6) * 13 + (j0 - j1 + 6)) * NHEAD + head];
            if (lab[m] != ln) acc -= 100.0f;
            sbuf[t][m] = acc;
            mx = fmaxf(mx, acc);
        }
        float sum = 0.0f;
        for (int m = 0; m < NWTOK; m++) {
            float e = expf(sbuf[t][m] - mx);
            sbuf[t][m] = e;
            sum += e;
        }
        float inv = 1.0f / sum;

        float o[HDIM];
#pragma unroll
        for (int d = 0; d < HDIM; d++) o[d] = 0.0f;
        for (int m = 0; m < NWTOK; m++) {
            float p = sbuf[t][m] * inv;
#pragma unroll
            for (int d = 0; d < HDIM; d++) o[d] += p * vs[m][d];
        }
        size_t orow = ((size_t)w * NWTOK + n) * CDIM + head * HDIM;
#pragma unroll
        for (int d = 0; d < HDIM; d++) out[orow + d] = o[d];
    }
}

// ---------------------------------------------------------------------------
// launch
// ---------------------------------------------------------------------------
extern "C" void kernel_launch(void* const* d_in, const int* in_sizes, int n_in,
                              void* d_out, int out_size) {
    const float* x     = (const float*)d_in[0];
    const float* n1w   = (const float*)d_in[1];
    const float* n1b   = (const float*)d_in[2];
    const float* qkvw  = (const float*)d_in[3];
    const float* qkvb  = (const float*)d_in[4];
    const float* rpb   = (const float*)d_in[5];
    const float* projw = (const float*)d_in[6];
    const float* projb = (const float*)d_in[7];
    const float* n2w   = (const float*)d_in[8];
    const float* n2b   = (const float*)d_in[9];
    const float* fc1w  = (const float*)d_in[10];
    const float* fc1b  = (const float*)d_in[11];
    const float* fc2w  = (const float*)d_in[12];
    const float* fc2b  = (const float*)d_in[13];
    float* out = (float*)d_out;

    float *p_xw, *p_qkv, *p_att, *p_x1, *p_y, *p_h;
    cudaGetSymbolAddress((void**)&p_xw,  g_xw);
    cudaGetSymbolAddress((void**)&p_qkv, g_qkv);
    cudaGetSymbolAddress((void**)&p_att, g_att);
    cudaGetSymbolAddress((void**)&p_x1,  g_x1);
    cudaGetSymbolAddress((void**)&p_y,   g_y);
    cudaGetSymbolAddress((void**)&p_h,   g_h);

    // 1) LN1 + cyclic shift + window partition
    ln_kernel<<<MTOK, 128>>>(x, n1w, n1b, p_xw, 1);

    // 2) QKV: [100352,384] @ [384,1152]
    tgemm_kernel<0><<<dim3(QKVDIM / 128, MTOK / 128), 256>>>(
        p_xw, qkvw, qkvb, p_qkv, nullptr, CDIM, QKVDIM);

    // 3) Windowed attention
    attn_kernel<<<BW * NHEAD, 64>>>(p_qkv, rpb, p_att);

    // 4) Proj + window reverse + unshift + residual
    tgemm_kernel<3><<<dim3(CDIM / 128, MTOK / 128), 256>>>(
        p_att, projw, projb, p_x1, x, CDIM, CDIM);

    // 5) LN2
    ln_kernel<<<MTOK, 128>>>(p_x1, n2w, n2b, p_y, 0);

    // 6) fc1 + exact GELU: [100352,384] @ [384,1536]
    tgemm_kernel<1><<<dim3(HIDDEN / 128, MTOK / 128), 256>>>(
        p_y, fc1w, fc1b, p_h, nullptr, CDIM, HIDDEN);

    // 7) fc2 + residual -> output: [100352,1536] @ [1536,384]
    tgemm_kernel<2><<<dim3(CDIM / 128, MTOK / 128), 256>>>(
        p_h, fc2w, fc2b, out, p_x1, HIDDEN, CDIM);
}